// round 14
// baseline (speedup 1.0000x reference)
#include <cuda_runtime.h>
#include <cstdint>

// Problem constants (fixed shapes per reference)
#define NTOK  (32 * 8192)   // 262144 tokens
#define DIM   256           // K
#define NEXP  16
#define POUT  64            // N
#define BM    128           // tokens per tile
#define CK    64            // K per chunk
#define NCH   (DIM / CK)    // 4 chunks

// ---------------- scratch ----------------
__device__ int g_sorted[NEXP][NTOK];   // per-expert slot regions
__device__ int g_cursor[NEXP];
// W in fp16, per-chunk sw128-swizzled tiles ([64 k][64 n] 128-B rows), 8 KB each.
__device__ unsigned char g_Wh[NEXP][NCH][8192];

// ---------------- helpers ----------------
__device__ __forceinline__ uint32_t s2u(const void* p) {
    uint32_t a;
    asm("{ .reg .u64 t; cvta.to.shared.u64 t, %1; cvt.u32.u64 %0, t; }" : "=r"(a) : "l"(p));
    return a;
}
__device__ __forceinline__ uint32_t sw128(uint32_t o) { return o ^ ((o >> 3) & 0x70); }

// pack two fp32 into fp16x2 (rn)
__device__ __forceinline__ uint32_t f2h2(float lo, float hi) {
    uint32_t r;
    asm("cvt.rn.f16x2.f32 %0, %1, %2;" : "=r"(r) : "f"(hi), "f"(lo));
    return r;
}

__device__ __forceinline__ void ldsm_x4(uint32_t addr, uint32_t r[4]) {
    asm volatile("ldmatrix.sync.aligned.m8n8.x4.shared.b16 {%0,%1,%2,%3}, [%4];"
                 : "=r"(r[0]), "=r"(r[1]), "=r"(r[2]), "=r"(r[3]) : "r"(addr));
}
__device__ __forceinline__ void ldsm_x4_t(uint32_t addr, uint32_t r[4]) {
    asm volatile("ldmatrix.sync.aligned.m8n8.x4.trans.shared.b16 {%0,%1,%2,%3}, [%4];"
                 : "=r"(r[0]), "=r"(r[1]), "=r"(r[2]), "=r"(r[3]) : "r"(addr));
}
__device__ __forceinline__ void mma16816h(float c[4], const uint32_t a[4],
                                          uint32_t b0, uint32_t b1) {
    asm volatile(
        "mma.sync.aligned.m16n8k16.row.col.f32.f16.f16.f32 "
        "{%0,%1,%2,%3}, {%4,%5,%6,%7}, {%8,%9}, {%0,%1,%2,%3};"
        : "+f"(c[0]), "+f"(c[1]), "+f"(c[2]), "+f"(c[3])
        : "r"(a[0]), "r"(a[1]), "r"(a[2]), "r"(a[3]), "r"(b0), "r"(b1));
}
__device__ __forceinline__ void cpasync16(uint32_t dst, const void* src) {
    asm volatile("cp.async.cg.shared.global [%0], [%1], 16;"
                 :: "r"(dst), "l"(src) : "memory");
}

// ---------------- prep: W fp16 convert + cursor zero ----------------------
__global__ void k_prep(const float* __restrict__ W) {
    if (blockIdx.x == 0 && threadIdx.x < NEXP) g_cursor[threadIdx.x] = 0;
    int e = blockIdx.x >> 2;
    int c = blockIdx.x & 3;
    int tid = threadIdx.x;
    const float* Wc = W + ((size_t)e * DIM + c * CK) * POUT;
#pragma unroll
    for (int i = 0; i < 4; i++) {
        int v = tid + i * 256;          // 0..1023 float4s over [64 k][16 n4]
        int kr = v >> 4, nq = v & 15;
        float4 f = *(const float4*)(Wc + (size_t)kr * POUT + nq * 4);
        uint2 hv;
        hv.x = f2h2(f.x, f.y);
        hv.y = f2h2(f.z, f.w);
        *(uint2*)(g_Wh[e][c] + sw128((uint32_t)(kr * 128 + nq * 8))) = hv;
    }
}

// ---------------- direct scatter (order within expert is free) ----------------
__global__ void k_scatter(const int* __restrict__ idx) {
    __shared__ int sc[NEXP];
    __shared__ int sbase[NEXP];
    int t = threadIdx.x;
    int lane = t & 31;
    if (t < NEXP) sc[t] = 0;
    __syncthreads();
    int i = blockIdx.x * blockDim.x + t;
    int e = idx[i];
    unsigned mask = __match_any_sync(0xffffffffu, e);
    int leader = __ffs(mask) - 1;
    int base = 0;
    if (lane == leader) base = atomicAdd(&sc[e], __popc(mask));
    base = __shfl_sync(0xffffffffu, base, leader);
    int local = base + __popc(mask & ((1u << lane) - 1u));
    __syncthreads();
    if (t < NEXP && sc[t] > 0) sbase[t] = atomicAdd(&g_cursor[t], sc[t]);
    __syncthreads();
    g_sorted[e][sbase[e] + local] = i;
}

// ---------------- smem layout ----------------
// [0:256)      bias (64 f32)
// [256:768)    rows (128 int)
// [1024:33792) A double buffer: 2 x 16 KB (fp16 [128 m][64 k], sw128)
// [33792:66560) B: whole W[e] fp16, 4 chunk-tiles x 8 KB, sw128
// epilogue:    C tile (128 x 68 f32 = 34.8 KB) overlays A (+ start of B)
#define SM_BIAS 0
#define SM_ROWS 256
#define SM_A    1024
#define SM_B    (SM_A + 32768)
#define SMEM_TOTAL (SM_B + 32768)   // 66560 -> 3 CTAs/SM
#define CS_STRIDE 68

// ---------------- grouped GEMM: fp16 single-term, pipelined, 3 CTA/SM ------
__global__ void __launch_bounds__(256, 3)
k_gemm_mma(const float* __restrict__ x, const float* __restrict__ bias,
           float* __restrict__ out) {
    // tile -> (expert, m0) via local prefix over final cursors (= counts)
    int tile = blockIdx.x;
    int e = -1, m0 = 0, accT = 0;
#pragma unroll
    for (int i = 0; i < NEXP; i++) {
        int cnt_i = g_cursor[i];
        int nt = (cnt_i + BM - 1) / BM;
        if (e < 0 && tile < accT + nt) { e = i; m0 = (tile - accT) * BM; }
        accT += nt;
    }
    if (e < 0) return;
    int cnt = g_cursor[e];

    extern __shared__ char smem[];
    uint32_t sb = s2u(smem);
    float* bias_s = (float*)(smem + SM_BIAS);
    int*   rows   = (int*)(smem + SM_ROWS);

    int tid = threadIdx.x;
    int wid = tid >> 5, L = tid & 31;

    if (tid < BM) {
        int m = m0 + tid;
        rows[tid] = (m < cnt) ? g_sorted[e][m] : -1;
    }
    if (tid < 16)
        *(float4*)(bias_s + tid * 4) = *(const float4*)(bias + e * POUT + tid * 4);

    // ---- B: one cp.async burst for the whole 32 KB W[e] ----
    {
        const unsigned char* src = g_Wh[e][0];
#pragma unroll
        for (int i = 0; i < 8; i++) {
            uint32_t o = (uint32_t)(tid + i * 256) * 16;
            cpasync16(sb + SM_B + o, src + o);
        }
        asm volatile("cp.async.commit_group;" ::: "memory");
    }
    __syncthreads();   // rows[] visible before gather

    // per-thread A-load coords
    const int am = tid >> 4;            // m sub-row (8 rows at +16 stride)
    const int aq = tid & 15;            // float4 within 64-float k chunk

    // warp tile: m32 x n32 (warp grid 4 x 2)
    const int mrow  = (wid & 3) * 32;
    const int nbase = (wid >> 2) * 32;
    int arow = (L & 15);
    int acol = (L >> 4) * 8;
    int brow = (L & 7) + ((L >> 3) & 1) * 8;
    int bcol = (L >> 4) * 8;

    float acc[2][4][4];
#pragma unroll
    for (int a = 0; a < 2; a++)
#pragma unroll
        for (int j = 0; j < 4; j++)
#pragma unroll
            for (int q = 0; q < 4; q++) acc[a][j][q] = 0.f;

    auto ldg_chunk = [&](int k0, uint2 ha[8]) {
#pragma unroll
        for (int i = 0; i < 8; i++) {
            int m = am + i * 16;
            int row = rows[m];
            float4 f = make_float4(0.f, 0.f, 0.f, 0.f);
            if (row >= 0) f = *(const float4*)(x + (size_t)row * DIM + k0 + aq * 4);
            ha[i].x = f2h2(f.x, f.y);
            ha[i].y = f2h2(f.z, f.w);
        }
    };
    auto sts_chunk = [&](const uint2 ha[8], uint32_t bufOff) {
#pragma unroll
        for (int i = 0; i < 8; i++) {
            int m = am + i * 16;
            *(uint2*)(smem + bufOff + sw128((uint32_t)(m * 128 + aq * 8))) = ha[i];
        }
    };

    // ---- prologue: stage A chunk 0 into buffer 0 ----
    uint2 ha[8];
    ldg_chunk(0, ha);
    sts_chunk(ha, SM_A);
    asm volatile("cp.async.wait_group 0;" ::: "memory");
    __syncthreads();

    for (int c = 0; c < NCH; c++) {
        const uint32_t A0 = sb + SM_A + (uint32_t)(c & 1) * 16384;
        const uint32_t B0 = sb + SM_B + (uint32_t)c * 8192;
        uint32_t nabuf = SM_A + (uint32_t)((c + 1) & 1) * 16384;

        // prefetch next A chunk into registers (hides under this chunk's MMAs)
        if (c + 1 < NCH) ldg_chunk((c + 1) * CK, ha);

        // ---- MMA phase: warp m32 x n32, 4 k16-steps ----
#pragma unroll
        for (int s = 0; s < 4; s++) {
            uint32_t av[2][4];
#pragma unroll
            for (int a = 0; a < 2; a++)
                ldsm_x4(A0 + sw128((uint32_t)((mrow + a * 16 + arow) * 128
                                              + (s * 16 + acol) * 2)), av[a]);
            uint32_t bv[2][4];
#pragma unroll
            for (int p = 0; p < 2; p++)
                ldsm_x4_t(B0 + sw128((uint32_t)((s * 16 + brow) * 128
                                                + (nbase + p * 16 + bcol) * 2)), bv[p]);
#pragma unroll
            for (int a = 0; a < 2; a++)
#pragma unroll
                for (int p = 0; p < 2; p++) {
                    mma16816h(acc[a][2 * p],     av[a], bv[p][0], bv[p][1]);
                    mma16816h(acc[a][2 * p + 1], av[a], bv[p][2], bv[p][3]);
                }
        }

        // stage next A chunk into the other buffer
        if (c + 1 < NCH) sts_chunk(ha, nabuf);
        __syncthreads();
    }

    // ---- epilogue: transpose through smem, coalesced scatter ----
    float* Cs = (float*)(smem + SM_A);
#pragma unroll
    for (int a = 0; a < 2; a++) {
        int r = mrow + a * 16 + (L >> 2);
        int cbase = nbase + (L & 3) * 2;
#pragma unroll
        for (int j = 0; j < 4; j++) {
            int cc = cbase + j * 8;
            *(float2*)(Cs + r * CS_STRIDE + cc)       = make_float2(acc[a][j][0], acc[a][j][1]);
            *(float2*)(Cs + (r + 8) * CS_STRIDE + cc) = make_float2(acc[a][j][2], acc[a][j][3]);
        }
    }
    __syncthreads();
    {
        int r = tid >> 1;
        int half = tid & 1;
        int row = rows[r];
        if (row >= 0) {
            float* op = out + (size_t)row * POUT;
#pragma unroll
            for (int q = 0; q < 8; q++) {
                int c4 = half * 8 + q;
                float4 v = *(float4*)(Cs + r * CS_STRIDE + c4 * 4);
                float4 bv = *(float4*)(bias_s + c4 * 4);
                v.x += bv.x; v.y += bv.y; v.z += bv.z; v.w += bv.w;
                *(float4*)(op + c4 * 4) = v;
            }
        }
    }
}

// ---------------- launch ----------------
extern "C" void kernel_launch(void* const* d_in, const int* in_sizes, int n_in,
                              void* d_out, int out_size) {
    const float* x   = (const float*)d_in[0];  // [32,8192,256]
    const float* W   = (const float*)d_in[1];  // [16,256,64]
    const float* b   = (const float*)d_in[2];  // [16,64]
    const int*   idx = (const int*)d_in[3];    // [32,8192]
    float* out = (float*)d_out;                // [32,8192,64]

    cudaFuncSetAttribute(k_gemm_mma, cudaFuncAttributeMaxDynamicSharedMemorySize, SMEM_TOTAL);

    k_prep<<<NEXP * NCH, 256>>>(W);
    k_scatter<<<NTOK / 256, 256>>>(idx);

    int max_tiles = NTOK / BM + NEXP;
    k_gemm_mma<<<max_tiles, 256, SMEM_TOTAL>>>(x, b, out);
}

// round 16
// speedup vs baseline: 1.1694x; 1.1694x over previous
#include <cuda_runtime.h>
#include <cstdint>

// Problem constants (fixed shapes per reference)
#define NTOK  (32 * 8192)   // 262144 tokens
#define DIM   256           // K
#define NEXP  16
#define POUT  64            // N
#define BM    128           // tokens per tile
#define CK    64            // K per chunk
#define NCH   4             // chunks
#define GRID  296           // 2 CTAs x 148 SMs (<= 2 x 152 on GB300: all co-resident)

// ---------------- scratch ----------------
__device__ int g_sorted[NEXP][NTOK];       // per-expert slot regions
__device__ int g_cursor[NEXP];
__device__ unsigned char g_Wh[NEXP][NCH][8192];  // W fp16, sw128 tile order
__device__ unsigned int g_barcnt[2];       // ever-growing grid-barrier counters

// ---------------- helpers ----------------
__device__ __forceinline__ uint32_t s2u(const void* p) {
    uint32_t a;
    asm("{ .reg .u64 t; cvta.to.shared.u64 t, %1; cvt.u32.u64 %0, t; }" : "=r"(a) : "l"(p));
    return a;
}
__device__ __forceinline__ uint32_t sw128(uint32_t o) { return o ^ ((o >> 3) & 0x70); }

__device__ __forceinline__ uint32_t f2h2(float lo, float hi) {
    uint32_t r;
    asm("cvt.rn.f16x2.f32 %0, %1, %2;" : "=r"(r) : "f"(hi), "f"(lo));
    return r;
}
__device__ __forceinline__ void ldsm_x4(uint32_t addr, uint32_t r[4]) {
    asm volatile("ldmatrix.sync.aligned.m8n8.x4.shared.b16 {%0,%1,%2,%3}, [%4];"
                 : "=r"(r[0]), "=r"(r[1]), "=r"(r[2]), "=r"(r[3]) : "r"(addr));
}
__device__ __forceinline__ void ldsm_x4_t(uint32_t addr, uint32_t r[4]) {
    asm volatile("ldmatrix.sync.aligned.m8n8.x4.trans.shared.b16 {%0,%1,%2,%3}, [%4];"
                 : "=r"(r[0]), "=r"(r[1]), "=r"(r[2]), "=r"(r[3]) : "r"(addr));
}
__device__ __forceinline__ void mma16816h(float c[4], const uint32_t a[4],
                                          uint32_t b0, uint32_t b1) {
    asm volatile(
        "mma.sync.aligned.m16n8k16.row.col.f32.f16.f16.f32 "
        "{%0,%1,%2,%3}, {%4,%5,%6,%7}, {%8,%9}, {%0,%1,%2,%3};"
        : "+f"(c[0]), "+f"(c[1]), "+f"(c[2]), "+f"(c[3])
        : "r"(a[0]), "r"(a[1]), "r"(a[2]), "r"(a[3]), "r"(b0), "r"(b1));
}
__device__ __forceinline__ void cpasync16(uint32_t dst, const void* src) {
    asm volatile("cp.async.cg.shared.global [%0], [%1], 16;"
                 :: "r"(dst), "l"(src) : "memory");
}

// grid barrier: cohort math on an ever-growing counter (no reset needed).
// Safe because all GRID CTAs are co-resident (occupancy-sized launch).
__device__ __forceinline__ void gridbar(int k) {
    __syncthreads();
    if (threadIdx.x == 0) {
        __threadfence();
        unsigned ticket = atomicAdd(&g_barcnt[k], 1u);
        unsigned target = (ticket / GRID + 1u) * GRID;
        unsigned cur;
        do {
            cur = atomicAdd(&g_barcnt[k], 0u);
            if ((int)(cur - target) >= 0) break;
            __nanosleep(64);
        } while (true);
    }
    __syncthreads();
    __threadfence();
}

// ---------------- smem layout ----------------
// [0:256)    bias (64 f32)
// [256:768)  rows (128 int)
// [1024:)    2 x { A 16K (fp16 [128 m][64 k], sw128) | B 8K (fp16 [64 k][64 n]) }
// epilogue:  C tile (128 x 68 f32 = 34.8 KB) overlays buffers
#define SM_BIAS 0
#define SM_ROWS 256
#define SM_BUF  1024
#define STAGE   24576
#define SMEM_TOTAL (SM_BUF + 2 * STAGE)   // 50176 -> 2 CTAs/SM
#define CS_STRIDE 68

// ---------------- persistent fused kernel ----------------
__global__ void __launch_bounds__(256, 2)
k_all(const float* __restrict__ x, const float* __restrict__ W,
      const float* __restrict__ bias, const int* __restrict__ idx,
      float* __restrict__ out) {
    extern __shared__ char smem[];
    uint32_t sb = s2u(smem);
    int tid = threadIdx.x;
    int cta = blockIdx.x;
    int wid = tid >> 5, L = tid & 31;

    // ======== P0: zero cursors + W fp16 prep ========
    if (cta == 0 && tid < NEXP) g_cursor[tid] = 0;
    if (cta < NEXP * NCH) {
        int e = cta >> 2, c = cta & 3;
        const float* Wc = W + ((size_t)e * DIM + c * CK) * POUT;
#pragma unroll
        for (int i = 0; i < 4; i++) {
            int v = tid + i * 256;
            int kr = v >> 4, nq = v & 15;
            float4 f = *(const float4*)(Wc + (size_t)kr * POUT + nq * 4);
            uint2 hv;
            hv.x = f2h2(f.x, f.y);
            hv.y = f2h2(f.z, f.w);
            *(uint2*)(g_Wh[e][c] + sw128((uint32_t)(kr * 128 + nq * 8))) = hv;
        }
    }
    gridbar(0);

    // ======== P1: scatter (grid-strided slices of 256 tokens) ========
    {
        __shared__ int sc[NEXP];
        __shared__ int sbase[NEXP];
        int lane = tid & 31;
        for (int s = cta; s < NTOK / 256; s += GRID) {
            if (tid < NEXP) sc[tid] = 0;
            __syncthreads();
            int i = s * 256 + tid;
            int e = idx[i];
            unsigned mask = __match_any_sync(0xffffffffu, e);
            int leader = __ffs(mask) - 1;
            int base = 0;
            if (lane == leader) base = atomicAdd(&sc[e], __popc(mask));
            base = __shfl_sync(0xffffffffu, base, leader);
            int local = base + __popc(mask & ((1u << lane) - 1u));
            __syncthreads();
            if (tid < NEXP && sc[tid] > 0) sbase[tid] = atomicAdd(&g_cursor[tid], sc[tid]);
            __syncthreads();
            g_sorted[e][sbase[e] + local] = i;
            __syncthreads();   // sc/sbase reused next slice
        }
    }
    gridbar(1);

    // ======== P2: GEMM tile loop ========
    float* bias_s = (float*)(smem + SM_BIAS);
    int*   rows   = (int*)(smem + SM_ROWS);

    // per-expert counts + total tiles
    int cnts[NEXP];
    int totalT = 0;
#pragma unroll
    for (int i = 0; i < NEXP; i++) {
        cnts[i] = g_cursor[i];
        totalT += (cnts[i] + BM - 1) / BM;
    }

    const int am = tid >> 4;            // m sub-row (8 rows at +16 stride)
    const int aq = tid & 15;            // float4 within 64-float k chunk
    const int mrow  = (wid & 3) * 32;   // warp tile m base (4 x 2 warp grid)
    const int nbase = (wid >> 2) * 32;  // warp tile n base
    const int arow = (L & 15);
    const int acol = (L >> 4) * 8;
    const int brow = (L & 7) + ((L >> 3) & 1) * 8;
    const int bcol = (L >> 4) * 8;

    for (int tile = cta; tile < totalT; tile += GRID) {
        // tile -> (expert, m0)
        int e = -1, m0 = 0, accT = 0;
#pragma unroll
        for (int i = 0; i < NEXP; i++) {
            int nt = (cnts[i] + BM - 1) / BM;
            if (e < 0 && tile < accT + nt) { e = i; m0 = (tile - accT) * BM; }
            accT += nt;
        }
        int cnt = cnts[e];

        if (tid < BM) {
            int m = m0 + tid;
            rows[tid] = (m < cnt) ? g_sorted[e][m] : -1;
        }
        if (tid < 16)
            *(float4*)(bias_s + tid * 4) = *(const float4*)(bias + e * POUT + tid * 4);

        float acc[2][4][4];
#pragma unroll
        for (int a = 0; a < 2; a++)
#pragma unroll
            for (int j = 0; j < 4; j++)
#pragma unroll
                for (int q = 0; q < 4; q++) acc[a][j][q] = 0.f;

        auto cp_b = [&](int c, uint32_t bufOff) {
            uint32_t bd = sb + bufOff + 16384;
            const unsigned char* src = g_Wh[e][c];
#pragma unroll
            for (int i = 0; i < 2; i++) {
                uint32_t o = (uint32_t)(tid + i * 256) * 16;   // 8 KB
                cpasync16(bd + o, src + o);
            }
            asm volatile("cp.async.commit_group;" ::: "memory");
        };
        auto ldg_chunk = [&](int k0, uint2 ha[8]) {
#pragma unroll
            for (int i = 0; i < 8; i++) {
                int m = am + i * 16;
                int row = rows[m];
                float4 f = make_float4(0.f, 0.f, 0.f, 0.f);
                if (row >= 0) f = *(const float4*)(x + (size_t)row * DIM + k0 + aq * 4);
                ha[i].x = f2h2(f.x, f.y);
                ha[i].y = f2h2(f.z, f.w);
            }
        };
        auto sts_chunk = [&](const uint2 ha[8], uint32_t bufOff) {
#pragma unroll
            for (int i = 0; i < 8; i++) {
                int m = am + i * 16;
                *(uint2*)(smem + bufOff + sw128((uint32_t)(m * 128 + aq * 8))) = ha[i];
            }
        };

        // prologue: stage chunk 0 into buffer 0 (rows visible after sync below)
        __syncthreads();
        uint2 ha[8];
        cp_b(0, SM_BUF);
        ldg_chunk(0, ha);
        sts_chunk(ha, SM_BUF);
        asm volatile("cp.async.wait_group 0;" ::: "memory");
        __syncthreads();

#pragma unroll
        for (int c = 0; c < NCH; c++) {
            uint32_t buf  = SM_BUF + (uint32_t)(c & 1) * STAGE;
            uint32_t nbuf = SM_BUF + (uint32_t)((c + 1) & 1) * STAGE;
            const uint32_t A0 = sb + buf;
            const uint32_t B0 = A0 + 16384;

            if (c + 1 < NCH) {
                cp_b(c + 1, nbuf);
                ldg_chunk((c + 1) * CK, ha);
            }

            // MMA: warp m32 x n32, 4 k16-steps
#pragma unroll
            for (int s = 0; s < 4; s++) {
                uint32_t av[2][4];
#pragma unroll
                for (int a = 0; a < 2; a++)
                    ldsm_x4(A0 + sw128((uint32_t)((mrow + a * 16 + arow) * 128
                                                  + (s * 16 + acol) * 2)), av[a]);
                uint32_t bv[2][4];
#pragma unroll
                for (int p = 0; p < 2; p++)
                    ldsm_x4_t(B0 + sw128((uint32_t)((s * 16 + brow) * 128
                                                    + (nbase + p * 16 + bcol) * 2)), bv[p]);
#pragma unroll
                for (int a = 0; a < 2; a++)
#pragma unroll
                    for (int p = 0; p < 2; p++) {
                        mma16816h(acc[a][2 * p],     av[a], bv[p][0], bv[p][1]);
                        mma16816h(acc[a][2 * p + 1], av[a], bv[p][2], bv[p][3]);
                    }
            }

            if (c + 1 < NCH) {
                sts_chunk(ha, nbuf);
                asm volatile("cp.async.wait_group 0;" ::: "memory");
            }
            __syncthreads();
        }

        // epilogue: transpose through smem, coalesced scatter
        float* Cs = (float*)(smem + SM_BUF);
#pragma unroll
        for (int a = 0; a < 2; a++) {
            int r = mrow + a * 16 + (L >> 2);
            int cb = nbase + (L & 3) * 2;
#pragma unroll
            for (int j = 0; j < 4; j++) {
                int cc = cb + j * 8;
                *(float2*)(Cs + r * CS_STRIDE + cc)       = make_float2(acc[a][j][0], acc[a][j][1]);
                *(float2*)(Cs + (r + 8) * CS_STRIDE + cc) = make_float2(acc[a][j][2], acc[a][j][3]);
            }
        }
        __syncthreads();
        {
            int r = tid >> 1;
            int half = tid & 1;
            int row = rows[r];
            if (row >= 0) {
                float* op = out + (size_t)row * POUT;
#pragma unroll
                for (int q = 0; q < 8; q++) {
                    int c4 = half * 8 + q;
                    float4 v = *(float4*)(Cs + r * CS_STRIDE + c4 * 4);
                    float4 bv = *(float4*)(bias_s + c4 * 4);
                    v.x += bv.x; v.y += bv.y; v.z += bv.z; v.w += bv.w;
                    *(float4*)(op + c4 * 4) = v;
                }
            }
        }
        __syncthreads();   // Cs / rows reused by next tile
    }
}

// ---------------- launch ----------------
extern "C" void kernel_launch(void* const* d_in, const int* in_sizes, int n_in,
                              void* d_out, int out_size) {
    const float* x   = (const float*)d_in[0];  // [32,8192,256]
    const float* W   = (const float*)d_in[1];  // [16,256,64]
    const float* b   = (const float*)d_in[2];  // [16,64]
    const int*   idx = (const int*)d_in[3];    // [32,8192]
    float* out = (float*)d_out;                // [32,8192,64]

    cudaFuncSetAttribute(k_all, cudaFuncAttributeMaxDynamicSharedMemorySize, SMEM_TOTAL);
    k_all<<<GRID, 256, SMEM_TOTAL>>>(x, W, b, idx, out);
}